// round 2
// baseline (speedup 1.0000x reference)
#include <cuda_runtime.h>
#include <cstdint>

// ---------------------------------------------------------------------------
// out[n] = elg[n] @ W @ eth[n],  N=32768, D=1024, fp32.
// sm_103 baseline-target build (no tcgen05): Ampere-style pipelined tf32
// mma.sync GEMM, tmp[m,d] = sum_e eth[m,e]*W[d,e], fused epilogue
// out[m] += sum_d tmp[m,d]*elg[m,d] held entirely in registers.
// CTA: 128x128 tile, BK=32, 3-stage cp.async, 8 warps (2m x 4n).
// ---------------------------------------------------------------------------

static constexpr int NROWS = 32768;
static constexpr int DDIM  = 1024;
static constexpr int BM = 128, BN = 128, BK = 32;
static constexpr int NTILES  = DDIM / BN;            // 8
static constexpr int KITERS  = DDIM / BK;            // 32
static constexpr int TOT_IT  = NTILES * KITERS;      // 256

static constexpr int ROWF    = 36;                   // 32 floats + 4 pad
static constexpr int TILE_B  = 128 * ROWF * 4;       // 18432 bytes (A or B tile)
static constexpr int STAGE_B = 2 * TILE_B;           // 36864
static constexpr int NSTAGES = 3;
static constexpr int SMEM_B  = NSTAGES * STAGE_B;    // 110592

__device__ __forceinline__ uint32_t smem_u32(const void* p) {
    uint32_t a;
    asm("{ .reg .u64 t; cvta.to.shared.u64 t, %1; cvt.u32.u64 %0, t; }" : "=r"(a) : "l"(p));
    return a;
}

__device__ __forceinline__ void cp16(uint32_t saddr, const void* g) {
    asm volatile("cp.async.cg.shared.global [%0], [%1], 16;\n" :: "r"(saddr), "l"(g));
}
#define CP_COMMIT() asm volatile("cp.async.commit_group;\n" ::: "memory")
#define CP_WAIT1()  asm volatile("cp.async.wait_group 1;\n" ::: "memory")
#define CP_WAIT0()  asm volatile("cp.async.wait_group 0;\n" ::: "memory")

__device__ __forceinline__ void ldsm4(uint32_t (&d)[4], uint32_t addr) {
    asm volatile("ldmatrix.sync.aligned.m8n8.x4.shared.b16 {%0,%1,%2,%3}, [%4];"
                 : "=r"(d[0]), "=r"(d[1]), "=r"(d[2]), "=r"(d[3]) : "r"(addr));
}

__device__ __forceinline__ uint32_t to_tf32(uint32_t x) {
    uint32_t y;
    asm("cvt.rna.tf32.f32 %0, %1;" : "=r"(y) : "f"(__uint_as_float(x)));
    return y;
}

__device__ __forceinline__ void mma_tf32(float (&c)[4], const uint32_t (&a)[4],
                                         uint32_t b0, uint32_t b1) {
    asm volatile(
        "mma.sync.aligned.m16n8k8.row.col.f32.tf32.tf32.f32 "
        "{%0,%1,%2,%3}, {%4,%5,%6,%7}, {%8,%9}, {%0,%1,%2,%3};"
        : "+f"(c[0]), "+f"(c[1]), "+f"(c[2]), "+f"(c[3])
        : "r"(a[0]), "r"(a[1]), "r"(a[2]), "r"(a[3]), "r"(b0), "r"(b1));
}

// ------------------------------- kernel ------------------------------------

__global__ void __launch_bounds__(256, 2)
bilinear_tf32_kernel(const float* __restrict__ elg, const float* __restrict__ eth,
                     const float* __restrict__ Wm, float* __restrict__ out)
{
    extern __shared__ __align__(16) float smem[];
    const uint32_t sbase = smem_u32(smem);

    const int tid    = threadIdx.x;
    const int lane   = tid & 31;
    const int wid    = tid >> 5;
    const int warp_m = wid >> 2;      // 0..1
    const int warp_n = wid & 3;       // 0..3
    const size_t row0 = (size_t)blockIdx.x * BM;

    // ldmatrix per-lane byte offsets (t = tile index, r = row within tile)
    const int t = lane >> 3, r = lane & 7;
    const uint32_t aoff = (uint32_t)((((t & 1) * 8 + r) * ROWF + (t >> 1) * 4) * 4);
    const uint32_t boff = (uint32_t)((((t >> 1) * 8 + r) * ROWF + (t & 1) * 4) * 4);
    const uint32_t a_warp = (uint32_t)(warp_m * 64 * ROWF * 4);
    const uint32_t b_warp = (uint32_t)(warp_n * 32 * ROWF * 4);

    float acc[4][4][4];
    #pragma unroll
    for (int i = 0; i < 4; ++i)
        #pragma unroll
        for (int j = 0; j < 4; ++j)
            #pragma unroll
            for (int k = 0; k < 4; ++k) acc[i][j][k] = 0.0f;

    float part[8];
    #pragma unroll
    for (int i = 0; i < 8; ++i) part[i] = 0.0f;

    // issue cp.async for flattened iteration jt
    auto issue = [&](int jt) {
        const int nt = jt >> 5, kc = jt & 31, st = jt % NSTAGES;
        const uint32_t ab = sbase + st * STAGE_B;
        const uint32_t bb = ab + TILE_B;
        #pragma unroll
        for (int u = 0; u < 4; ++u) {
            const int idx = tid + u * 256;          // 0..1023
            const int m = idx >> 3, c4 = idx & 7;
            cp16(ab + (uint32_t)((m * ROWF + c4 * 4) * 4),
                 eth + (row0 + m) * (size_t)DDIM + kc * BK + c4 * 4);
        }
        #pragma unroll
        for (int u = 0; u < 4; ++u) {
            const int idx = tid + u * 256;
            const int n = idx >> 3, c4 = idx & 7;
            cp16(bb + (uint32_t)((n * ROWF + c4 * 4) * 4),
                 Wm + (size_t)(nt * BN + n) * DDIM + kc * BK + c4 * 4);
        }
        CP_COMMIT();
    };

    issue(0);
    issue(1);

    int cur = 0;
    for (int it = 0; it < TOT_IT; ++it) {
        const int nt = it >> 5, kc = it & 31;

        if (it == TOT_IT - 1) { CP_WAIT0(); } else { CP_WAIT1(); }
        __syncthreads();

        if (it + 2 < TOT_IT) issue(it + 2);

        const uint32_t abase = sbase + cur * STAGE_B + a_warp + aoff;
        const uint32_t bbase = sbase + cur * STAGE_B + TILE_B + b_warp + boff;

        #pragma unroll
        for (int ks = 0; ks < 4; ++ks) {
            uint32_t afr[4][4];
            #pragma unroll
            for (int fm = 0; fm < 4; ++fm) {
                ldsm4(afr[fm], abase + (uint32_t)(fm * 16 * ROWF * 4 + ks * 32));
                #pragma unroll
                for (int q = 0; q < 4; ++q) afr[fm][q] = to_tf32(afr[fm][q]);
            }
            uint32_t bfr[2][4];
            #pragma unroll
            for (int fp = 0; fp < 2; ++fp) {
                ldsm4(bfr[fp], bbase + (uint32_t)(fp * 16 * ROWF * 4 + ks * 32));
                #pragma unroll
                for (int q = 0; q < 4; ++q) bfr[fp][q] = to_tf32(bfr[fp][q]);
            }
            #pragma unroll
            for (int fm = 0; fm < 4; ++fm)
                #pragma unroll
                for (int fn = 0; fn < 4; ++fn)
                    mma_tf32(acc[fm][fn], afr[fm],
                             bfr[fn >> 1][(fn & 1) * 2 + 0],
                             bfr[fn >> 1][(fn & 1) * 2 + 1]);
        }
        cur = (cur + 1 == NSTAGES) ? 0 : cur + 1;

        // fused epilogue at the end of each n-tile: fold acc into row partials
        if (kc == KITERS - 1) {
            const int q = lane & 3, grp = lane >> 2;
            #pragma unroll
            for (int fm = 0; fm < 4; ++fm) {
                const size_t rowA = row0 + warp_m * 64 + fm * 16 + grp;
                #pragma unroll
                for (int fn = 0; fn < 4; ++fn) {
                    const int col = nt * BN + warp_n * 32 + fn * 8 + q * 2;
                    const float2 e0 = *reinterpret_cast<const float2*>(
                        elg + rowA * (size_t)DDIM + col);
                    const float2 e1 = *reinterpret_cast<const float2*>(
                        elg + (rowA + 8) * (size_t)DDIM + col);
                    part[fm * 2 + 0] = fmaf(acc[fm][fn][0], e0.x,
                                       fmaf(acc[fm][fn][1], e0.y, part[fm * 2 + 0]));
                    part[fm * 2 + 1] = fmaf(acc[fm][fn][2], e1.x,
                                       fmaf(acc[fm][fn][3], e1.y, part[fm * 2 + 1]));
                    acc[fm][fn][0] = 0.0f; acc[fm][fn][1] = 0.0f;
                    acc[fm][fn][2] = 0.0f; acc[fm][fn][3] = 0.0f;
                }
            }
        }
    }

    // cross-lane + cross-warp reduction (smem stages are dead now; reuse)
    __syncthreads();
    #pragma unroll
    for (int i = 0; i < 8; ++i) {
        part[i] += __shfl_xor_sync(0xFFFFFFFFu, part[i], 1);
        part[i] += __shfl_xor_sync(0xFFFFFFFFu, part[i], 2);
    }
    float* red = smem;                // [4][128]
    if ((lane & 3) == 0) {
        const int grp = lane >> 2;
        #pragma unroll
        for (int fm = 0; fm < 4; ++fm) {
            red[warp_n * 128 + warp_m * 64 + fm * 16 + grp]     = part[fm * 2 + 0];
            red[warp_n * 128 + warp_m * 64 + fm * 16 + grp + 8] = part[fm * 2 + 1];
        }
    }
    __syncthreads();
    if (tid < BM)
        out[row0 + tid] = red[tid] + red[128 + tid] + red[256 + tid] + red[384 + tid];
}

// ------------------------------- launch ------------------------------------

extern "C" void kernel_launch(void* const* d_in, const int* in_sizes, int n_in,
                              void* d_out, int out_size) {
    (void)in_sizes; (void)n_in; (void)out_size;
    const float* elg = (const float*)d_in[0];
    const float* eth = (const float*)d_in[1];
    const float* Wm  = (const float*)d_in[2];
    float* out = (float*)d_out;

    cudaFuncSetAttribute(bilinear_tf32_kernel,
                         cudaFuncAttributeMaxDynamicSharedMemorySize, SMEM_B);
    bilinear_tf32_kernel<<<NROWS / BM, 256, SMEM_B>>>(elg, eth, Wm, out);
}

// round 3
// speedup vs baseline: 1.1114x; 1.1114x over previous
#include <cuda_runtime.h>
#include <cstdint>

// ---------------------------------------------------------------------------
// out[n] = elg[n] @ W @ eth[n],  N=32768, D=1024, fp32.
// R3: same pipelined tf32 mma.sync GEMM as R2, but the cvt.rna.tf32 rounding
// is hoisted into a prepass kernel (eth, W rounded once into __device__
// scratch). Inner loop is pure ldmatrix -> mma. Math bit-identical to R2.
// ---------------------------------------------------------------------------

static constexpr int NROWS = 32768;
static constexpr int DDIM  = 1024;
static constexpr int BM = 128, BN = 128, BK = 32;
static constexpr int NTILES  = DDIM / BN;            // 8
static constexpr int KITERS  = DDIM / BK;            // 32
static constexpr int TOT_IT  = NTILES * KITERS;      // 256

static constexpr int ROWF    = 36;                   // 32 floats + 4 pad
static constexpr int TILE_B  = 128 * ROWF * 4;       // 18432 bytes
static constexpr int STAGE_B = 2 * TILE_B;           // 36864
static constexpr int NSTAGES = 3;
static constexpr int SMEM_B  = NSTAGES * STAGE_B;    // 110592

// tf32-rounded copies (prepass output). Static device scratch — no allocs.
__device__ float g_eth_t[(size_t)NROWS * DDIM];      // 128 MB
__device__ float g_W_t[(size_t)DDIM * DDIM];         // 4 MB

__device__ __forceinline__ uint32_t smem_u32(const void* p) {
    uint32_t a;
    asm("{ .reg .u64 t; cvta.to.shared.u64 t, %1; cvt.u32.u64 %0, t; }" : "=r"(a) : "l"(p));
    return a;
}

__device__ __forceinline__ void cp16(uint32_t saddr, const void* g) {
    asm volatile("cp.async.cg.shared.global [%0], [%1], 16;\n" :: "r"(saddr), "l"(g));
}
#define CP_COMMIT() asm volatile("cp.async.commit_group;\n" ::: "memory")
#define CP_WAIT1()  asm volatile("cp.async.wait_group 1;\n" ::: "memory")
#define CP_WAIT0()  asm volatile("cp.async.wait_group 0;\n" ::: "memory")

__device__ __forceinline__ void ldsm4(uint32_t (&d)[4], uint32_t addr) {
    asm volatile("ldmatrix.sync.aligned.m8n8.x4.shared.b16 {%0,%1,%2,%3}, [%4];"
                 : "=r"(d[0]), "=r"(d[1]), "=r"(d[2]), "=r"(d[3]) : "r"(addr));
}

__device__ __forceinline__ float rna_tf32(float x) {
    uint32_t y;
    asm("cvt.rna.tf32.f32 %0, %1;" : "=r"(y) : "f"(x));
    return __uint_as_float(y);
}

__device__ __forceinline__ void mma_tf32(float (&c)[4], const uint32_t (&a)[4],
                                         uint32_t b0, uint32_t b1) {
    asm volatile(
        "mma.sync.aligned.m16n8k8.row.col.f32.tf32.tf32.f32 "
        "{%0,%1,%2,%3}, {%4,%5,%6,%7}, {%8,%9}, {%0,%1,%2,%3};"
        : "+f"(c[0]), "+f"(c[1]), "+f"(c[2]), "+f"(c[3])
        : "r"(a[0]), "r"(a[1]), "r"(a[2]), "r"(a[3]), "r"(b0), "r"(b1));
}

// --------------------------- prepass: RNA round ----------------------------

__global__ void __launch_bounds__(256)
round_tf32_kernel(const float* __restrict__ src, float* __restrict__ dst, int n4)
{
    const int stride = gridDim.x * blockDim.x;
    for (int i = blockIdx.x * blockDim.x + threadIdx.x; i < n4; i += stride) {
        float4 v = reinterpret_cast<const float4*>(src)[i];
        v.x = rna_tf32(v.x); v.y = rna_tf32(v.y);
        v.z = rna_tf32(v.z); v.w = rna_tf32(v.w);
        reinterpret_cast<float4*>(dst)[i] = v;
    }
}

// ------------------------------- main kernel -------------------------------

__global__ void __launch_bounds__(256, 2)
bilinear_tf32_kernel(const float* __restrict__ elg, const float* __restrict__ eth,
                     const float* __restrict__ Wm, float* __restrict__ out)
{
    extern __shared__ __align__(16) float smem[];
    const uint32_t sbase = smem_u32(smem);

    const int tid    = threadIdx.x;
    const int lane   = tid & 31;
    const int wid    = tid >> 5;
    const int warp_m = wid >> 2;      // 0..1
    const int warp_n = wid & 3;       // 0..3
    const size_t row0 = (size_t)blockIdx.x * BM;

    // ldmatrix per-lane byte offsets
    const int t = lane >> 3, r = lane & 7;
    const uint32_t aoff = (uint32_t)((((t & 1) * 8 + r) * ROWF + (t >> 1) * 4) * 4);
    const uint32_t boff = (uint32_t)((((t >> 1) * 8 + r) * ROWF + (t & 1) * 4) * 4);
    const uint32_t a_warp = (uint32_t)(warp_m * 64 * ROWF * 4);
    const uint32_t b_warp = (uint32_t)(warp_n * 32 * ROWF * 4);

    float acc[4][4][4];
    #pragma unroll
    for (int i = 0; i < 4; ++i)
        #pragma unroll
        for (int j = 0; j < 4; ++j)
            #pragma unroll
            for (int k = 0; k < 4; ++k) acc[i][j][k] = 0.0f;

    float part[8];
    #pragma unroll
    for (int i = 0; i < 8; ++i) part[i] = 0.0f;

    auto issue = [&](int jt) {
        const int nt = jt >> 5, kc = jt & 31, st = jt % NSTAGES;
        const uint32_t ab = sbase + st * STAGE_B;
        const uint32_t bb = ab + TILE_B;
        #pragma unroll
        for (int u = 0; u < 4; ++u) {
            const int idx = tid + u * 256;
            const int m = idx >> 3, c4 = idx & 7;
            cp16(ab + (uint32_t)((m * ROWF + c4 * 4) * 4),
                 eth + (row0 + m) * (size_t)DDIM + kc * BK + c4 * 4);
        }
        #pragma unroll
        for (int u = 0; u < 4; ++u) {
            const int idx = tid + u * 256;
            const int n = idx >> 3, c4 = idx & 7;
            cp16(bb + (uint32_t)((n * ROWF + c4 * 4) * 4),
                 Wm + (size_t)(nt * BN + n) * DDIM + kc * BK + c4 * 4);
        }
        CP_COMMIT();
    };

    issue(0);
    issue(1);

    int cur = 0;
    for (int it = 0; it < TOT_IT; ++it) {
        const int nt = it >> 5, kc = it & 31;

        if (it == TOT_IT - 1) { CP_WAIT0(); } else { CP_WAIT1(); }
        __syncthreads();

        if (it + 2 < TOT_IT) issue(it + 2);

        const uint32_t abase = sbase + cur * STAGE_B + a_warp + aoff;
        const uint32_t bbase = sbase + cur * STAGE_B + TILE_B + b_warp + boff;

        #pragma unroll
        for (int ks = 0; ks < 4; ++ks) {
            uint32_t afr[4][4];
            #pragma unroll
            for (int fm = 0; fm < 4; ++fm)
                ldsm4(afr[fm], abase + (uint32_t)(fm * 16 * ROWF * 4 + ks * 32));
            uint32_t bfr[2][4];
            #pragma unroll
            for (int fp = 0; fp < 2; ++fp)
                ldsm4(bfr[fp], bbase + (uint32_t)(fp * 16 * ROWF * 4 + ks * 32));
            #pragma unroll
            for (int fm = 0; fm < 4; ++fm)
                #pragma unroll
                for (int fn = 0; fn < 4; ++fn)
                    mma_tf32(acc[fm][fn], afr[fm],
                             bfr[fn >> 1][(fn & 1) * 2 + 0],
                             bfr[fn >> 1][(fn & 1) * 2 + 1]);
        }
        cur = (cur + 1 == NSTAGES) ? 0 : cur + 1;

        if (kc == KITERS - 1) {
            const int q = lane & 3, grp = lane >> 2;
            #pragma unroll
            for (int fm = 0; fm < 4; ++fm) {
                const size_t rowA = row0 + warp_m * 64 + fm * 16 + grp;
                #pragma unroll
                for (int fn = 0; fn < 4; ++fn) {
                    const int col = nt * BN + warp_n * 32 + fn * 8 + q * 2;
                    const float2 e0 = *reinterpret_cast<const float2*>(
                        elg + rowA * (size_t)DDIM + col);
                    const float2 e1 = *reinterpret_cast<const float2*>(
                        elg + (rowA + 8) * (size_t)DDIM + col);
                    part[fm * 2 + 0] = fmaf(acc[fm][fn][0], e0.x,
                                       fmaf(acc[fm][fn][1], e0.y, part[fm * 2 + 0]));
                    part[fm * 2 + 1] = fmaf(acc[fm][fn][2], e1.x,
                                       fmaf(acc[fm][fn][3], e1.y, part[fm * 2 + 1]));
                    acc[fm][fn][0] = 0.0f; acc[fm][fn][1] = 0.0f;
                    acc[fm][fn][2] = 0.0f; acc[fm][fn][3] = 0.0f;
                }
            }
        }
    }

    __syncthreads();
    #pragma unroll
    for (int i = 0; i < 8; ++i) {
        part[i] += __shfl_xor_sync(0xFFFFFFFFu, part[i], 1);
        part[i] += __shfl_xor_sync(0xFFFFFFFFu, part[i], 2);
    }
    float* red = smem;                // [4][128]
    if ((lane & 3) == 0) {
        const int grp = lane >> 2;
        #pragma unroll
        for (int fm = 0; fm < 4; ++fm) {
            red[warp_n * 128 + warp_m * 64 + fm * 16 + grp]     = part[fm * 2 + 0];
            red[warp_n * 128 + warp_m * 64 + fm * 16 + grp + 8] = part[fm * 2 + 1];
        }
    }
    __syncthreads();
    if (tid < BM)
        out[row0 + tid] = red[tid] + red[128 + tid] + red[256 + tid] + red[384 + tid];
}

// ------------------------------- launch ------------------------------------

extern "C" void kernel_launch(void* const* d_in, const int* in_sizes, int n_in,
                              void* d_out, int out_size) {
    (void)in_sizes; (void)n_in; (void)out_size;
    const float* elg = (const float*)d_in[0];
    const float* eth = (const float*)d_in[1];
    const float* Wm  = (const float*)d_in[2];
    float* out = (float*)d_out;

    float* eth_t = nullptr;
    float* W_t   = nullptr;
    cudaGetSymbolAddress((void**)&eth_t, g_eth_t);
    cudaGetSymbolAddress((void**)&W_t,   g_W_t);

    // Prepass: RNA-round eth and W to tf32 once.
    round_tf32_kernel<<<1184, 256>>>(eth, eth_t, (NROWS * DDIM) / 4);
    round_tf32_kernel<<<148, 256>>>(Wm, W_t, (DDIM * DDIM) / 4);

    cudaFuncSetAttribute(bilinear_tf32_kernel,
                         cudaFuncAttributeMaxDynamicSharedMemorySize, SMEM_B);
    bilinear_tf32_kernel<<<NROWS / BM, 256, SMEM_B>>>(elg, eth_t, W_t, out);
}

// round 4
// speedup vs baseline: 1.4789x; 1.3307x over previous
#include <cuda_runtime.h>
#include <cstdint>

// ---------------------------------------------------------------------------
// out[n] = elg[n] @ W @ eth[n],  N=32768, D=1024, fp32.
// R4: tf32 mma.sync GEMM with fat warps. CTA 256x128 tile, 8 warps (4m x 2n),
// warp tile 64x64 (32 MMA / 8 ldmatrix per k-slice), BK=32, 4-stage cp.async.
// Prepass RNA-rounds eth and W once (math identical to R3).
// ---------------------------------------------------------------------------

static constexpr int NROWS = 32768;
static constexpr int DDIM  = 1024;
static constexpr int BM = 256, BN = 128, BK = 32;
static constexpr int NTILES  = DDIM / BN;            // 8
static constexpr int KITERS  = DDIM / BK;            // 32
static constexpr int TOT_IT  = NTILES * KITERS;      // 256

static constexpr int ROWF     = 36;                  // 32 floats + 4 pad
static constexpr int A_TILE_B = BM * ROWF * 4;       // 36864
static constexpr int B_TILE_B = BN * ROWF * 4;       // 18432
static constexpr int STAGE_B  = A_TILE_B + B_TILE_B; // 55296
static constexpr int NSTAGES  = 4;
static constexpr int SMEM_B   = NSTAGES * STAGE_B;   // 221184

// tf32-rounded copies (prepass output). Static device scratch — no allocs.
__device__ float g_eth_t[(size_t)NROWS * DDIM];      // 128 MB
__device__ float g_W_t[(size_t)DDIM * DDIM];         // 4 MB

__device__ __forceinline__ uint32_t smem_u32(const void* p) {
    uint32_t a;
    asm("{ .reg .u64 t; cvta.to.shared.u64 t, %1; cvt.u32.u64 %0, t; }" : "=r"(a) : "l"(p));
    return a;
}

__device__ __forceinline__ void cp16(uint32_t saddr, const void* g) {
    asm volatile("cp.async.cg.shared.global [%0], [%1], 16;\n" :: "r"(saddr), "l"(g));
}
#define CP_COMMIT() asm volatile("cp.async.commit_group;\n" ::: "memory")
#define CP_WAIT2()  asm volatile("cp.async.wait_group 2;\n" ::: "memory")
#define CP_WAIT1()  asm volatile("cp.async.wait_group 1;\n" ::: "memory")
#define CP_WAIT0()  asm volatile("cp.async.wait_group 0;\n" ::: "memory")

__device__ __forceinline__ void ldsm4(uint32_t (&d)[4], uint32_t addr) {
    asm volatile("ldmatrix.sync.aligned.m8n8.x4.shared.b16 {%0,%1,%2,%3}, [%4];"
                 : "=r"(d[0]), "=r"(d[1]), "=r"(d[2]), "=r"(d[3]) : "r"(addr));
}

__device__ __forceinline__ float rna_tf32(float x) {
    uint32_t y;
    asm("cvt.rna.tf32.f32 %0, %1;" : "=r"(y) : "f"(x));
    return __uint_as_float(y);
}

__device__ __forceinline__ void mma_tf32(float (&c)[4], const uint32_t (&a)[4],
                                         uint32_t b0, uint32_t b1) {
    asm volatile(
        "mma.sync.aligned.m16n8k8.row.col.f32.tf32.tf32.f32 "
        "{%0,%1,%2,%3}, {%4,%5,%6,%7}, {%8,%9}, {%0,%1,%2,%3};"
        : "+f"(c[0]), "+f"(c[1]), "+f"(c[2]), "+f"(c[3])
        : "r"(a[0]), "r"(a[1]), "r"(a[2]), "r"(a[3]), "r"(b0), "r"(b1));
}

// --------------------------- prepass: RNA round ----------------------------

__global__ void __launch_bounds__(256)
round_tf32_kernel(const float* __restrict__ src, float* __restrict__ dst, int n4)
{
    const int stride = gridDim.x * blockDim.x;
    for (int i = blockIdx.x * blockDim.x + threadIdx.x; i < n4; i += stride) {
        float4 v = reinterpret_cast<const float4*>(src)[i];
        v.x = rna_tf32(v.x); v.y = rna_tf32(v.y);
        v.z = rna_tf32(v.z); v.w = rna_tf32(v.w);
        reinterpret_cast<float4*>(dst)[i] = v;
    }
}

// ------------------------------- main kernel -------------------------------

__global__ void __launch_bounds__(256, 1)
bilinear_tf32_kernel(const float* __restrict__ elg, const float* __restrict__ eth,
                     const float* __restrict__ Wm, float* __restrict__ out)
{
    extern __shared__ __align__(16) float smem[];
    const uint32_t sbase = smem_u32(smem);

    const int tid    = threadIdx.x;
    const int lane   = tid & 31;
    const int wid    = tid >> 5;
    const int warp_m = wid >> 1;      // 0..3
    const int warp_n = wid & 1;       // 0..1
    const size_t row0 = (size_t)blockIdx.x * BM;

    // ldmatrix per-lane byte offsets (t = tile index, r = row within tile)
    const int t = lane >> 3, r = lane & 7;
    const uint32_t aoff = (uint32_t)((((t & 1) * 8 + r) * ROWF + (t >> 1) * 4) * 4);
    const uint32_t boff = (uint32_t)((((t >> 1) * 8 + r) * ROWF + (t & 1) * 4) * 4);
    const uint32_t a_warp = (uint32_t)(warp_m * 64 * ROWF * 4);
    const uint32_t b_warp = (uint32_t)(warp_n * 64 * ROWF * 4);

    float acc[4][8][4];
    #pragma unroll
    for (int i = 0; i < 4; ++i)
        #pragma unroll
        for (int j = 0; j < 8; ++j)
            #pragma unroll
            for (int k = 0; k < 4; ++k) acc[i][j][k] = 0.0f;

    float part[8];
    #pragma unroll
    for (int i = 0; i < 8; ++i) part[i] = 0.0f;

    auto issue = [&](int jt) {
        const int nt = jt >> 5, kc = jt & 31, st = jt & (NSTAGES - 1);
        const uint32_t ab = sbase + st * STAGE_B;
        const uint32_t bb = ab + A_TILE_B;
        #pragma unroll
        for (int u = 0; u < 8; ++u) {               // A: 256 rows x 8 float4
            const int idx = tid + u * 256;          // 0..2047
            const int m = idx >> 3, c4 = idx & 7;
            cp16(ab + (uint32_t)((m * ROWF + c4 * 4) * 4),
                 eth + (row0 + m) * (size_t)DDIM + kc * BK + c4 * 4);
        }
        #pragma unroll
        for (int u = 0; u < 4; ++u) {               // B: 128 rows x 8 float4
            const int idx = tid + u * 256;
            const int n = idx >> 3, c4 = idx & 7;
            cp16(bb + (uint32_t)((n * ROWF + c4 * 4) * 4),
                 Wm + (size_t)(nt * BN + n) * DDIM + kc * BK + c4 * 4);
        }
        CP_COMMIT();
    };

    issue(0);
    issue(1);
    issue(2);

    for (int it = 0; it < TOT_IT; ++it) {
        const int nt = it >> 5, kc = it & 31;
        const int cur = it & (NSTAGES - 1);

        if      (it <  TOT_IT - 2) { CP_WAIT2(); }
        else if (it == TOT_IT - 2) { CP_WAIT1(); }
        else                       { CP_WAIT0(); }
        __syncthreads();

        if (it + 3 < TOT_IT) issue(it + 3);

        const uint32_t abase = sbase + cur * STAGE_B + a_warp + aoff;
        const uint32_t bbase = sbase + cur * STAGE_B + A_TILE_B + b_warp + boff;

        #pragma unroll
        for (int ks = 0; ks < 4; ++ks) {
            uint32_t afr[4][4];
            #pragma unroll
            for (int fm = 0; fm < 4; ++fm)
                ldsm4(afr[fm], abase + (uint32_t)(fm * 16 * ROWF * 4 + ks * 32));
            uint32_t bfr[4][4];
            #pragma unroll
            for (int fp = 0; fp < 4; ++fp)
                ldsm4(bfr[fp], bbase + (uint32_t)(fp * 16 * ROWF * 4 + ks * 32));
            #pragma unroll
            for (int fm = 0; fm < 4; ++fm)
                #pragma unroll
                for (int fn = 0; fn < 8; ++fn)
                    mma_tf32(acc[fm][fn], afr[fm],
                             bfr[fn >> 1][(fn & 1) * 2 + 0],
                             bfr[fn >> 1][(fn & 1) * 2 + 1]);
        }

        // fused epilogue at the end of each n-tile: fold acc into row partials
        if (kc == KITERS - 1) {
            const int q = lane & 3, grp = lane >> 2;
            #pragma unroll
            for (int fm = 0; fm < 4; ++fm) {
                const size_t rowA = row0 + warp_m * 64 + fm * 16 + grp;
                #pragma unroll
                for (int fn = 0; fn < 8; ++fn) {
                    const int col = nt * BN + warp_n * 64 + fn * 8 + q * 2;
                    const float2 e0 = *reinterpret_cast<const float2*>(
                        elg + rowA * (size_t)DDIM + col);
                    const float2 e1 = *reinterpret_cast<const float2*>(
                        elg + (rowA + 8) * (size_t)DDIM + col);
                    part[fm * 2 + 0] = fmaf(acc[fm][fn][0], e0.x,
                                       fmaf(acc[fm][fn][1], e0.y, part[fm * 2 + 0]));
                    part[fm * 2 + 1] = fmaf(acc[fm][fn][2], e1.x,
                                       fmaf(acc[fm][fn][3], e1.y, part[fm * 2 + 1]));
                    acc[fm][fn][0] = 0.0f; acc[fm][fn][1] = 0.0f;
                    acc[fm][fn][2] = 0.0f; acc[fm][fn][3] = 0.0f;
                }
            }
        }
    }

    // cross-lane + cross-warp reduction (smem stages are dead now; reuse)
    __syncthreads();
    #pragma unroll
    for (int i = 0; i < 8; ++i) {
        part[i] += __shfl_xor_sync(0xFFFFFFFFu, part[i], 1);
        part[i] += __shfl_xor_sync(0xFFFFFFFFu, part[i], 2);
    }
    float* red = smem;                // [2][256]
    if ((lane & 3) == 0) {
        const int grp = lane >> 2;
        #pragma unroll
        for (int fm = 0; fm < 4; ++fm) {
            red[warp_n * 256 + warp_m * 64 + fm * 16 + grp]     = part[fm * 2 + 0];
            red[warp_n * 256 + warp_m * 64 + fm * 16 + grp + 8] = part[fm * 2 + 1];
        }
    }
    __syncthreads();
    out[row0 + tid] = red[tid] + red[256 + tid];
}

// ------------------------------- launch ------------------------------------

extern "C" void kernel_launch(void* const* d_in, const int* in_sizes, int n_in,
                              void* d_out, int out_size) {
    (void)in_sizes; (void)n_in; (void)out_size;
    const float* elg = (const float*)d_in[0];
    const float* eth = (const float*)d_in[1];
    const float* Wm  = (const float*)d_in[2];
    float* out = (float*)d_out;

    float* eth_t = nullptr;
    float* W_t   = nullptr;
    cudaGetSymbolAddress((void**)&eth_t, g_eth_t);
    cudaGetSymbolAddress((void**)&W_t,   g_W_t);

    // Prepass: RNA-round eth and W to tf32 once.
    round_tf32_kernel<<<1184, 256>>>(eth, eth_t, (NROWS * DDIM) / 4);
    round_tf32_kernel<<<148, 256>>>(Wm, W_t, (DDIM * DDIM) / 4);

    cudaFuncSetAttribute(bilinear_tf32_kernel,
                         cudaFuncAttributeMaxDynamicSharedMemorySize, SMEM_B);
    bilinear_tf32_kernel<<<NROWS / BM, 256, SMEM_B>>>(elg, eth_t, W_t, out);
}

// round 5
// speedup vs baseline: 1.6759x; 1.1332x over previous
#include <cuda_runtime.h>
#include <cstdint>

// ---------------------------------------------------------------------------
// out[n] = elg[n] @ W @ eth[n],  N=32768, D=1024, fp32.
// R5: fat warps x occupancy. CTA 128x128 tile, 4 warps (2m x 2n), warp tile
// 64x64 (32 MMA / 8 ldmatrix per k-slice), BK=32, 3-stage cp.async,
// 2 CTAs/SM (16 warps/SM). Prepass RNA-rounds eth and W once.
// ---------------------------------------------------------------------------

static constexpr int NROWS = 32768;
static constexpr int DDIM  = 1024;
static constexpr int BM = 128, BN = 128, BK = 32;
static constexpr int NTILES  = DDIM / BN;            // 8
static constexpr int KITERS  = DDIM / BK;            // 32
static constexpr int TOT_IT  = NTILES * KITERS;      // 256

static constexpr int ROWF     = 36;                  // 32 floats + 4 pad
static constexpr int A_TILE_B = BM * ROWF * 4;       // 18432
static constexpr int B_TILE_B = BN * ROWF * 4;       // 18432
static constexpr int STAGE_B  = A_TILE_B + B_TILE_B; // 36864
static constexpr int NSTAGES  = 3;
static constexpr int SMEM_B   = NSTAGES * STAGE_B;   // 110592

// tf32-rounded copies (prepass output). Static device scratch — no allocs.
__device__ float g_eth_t[(size_t)NROWS * DDIM];      // 128 MB
__device__ float g_W_t[(size_t)DDIM * DDIM];         // 4 MB

__device__ __forceinline__ uint32_t smem_u32(const void* p) {
    uint32_t a;
    asm("{ .reg .u64 t; cvta.to.shared.u64 t, %1; cvt.u32.u64 %0, t; }" : "=r"(a) : "l"(p));
    return a;
}

__device__ __forceinline__ void cp16(uint32_t saddr, const void* g) {
    asm volatile("cp.async.cg.shared.global [%0], [%1], 16;\n" :: "r"(saddr), "l"(g));
}
#define CP_COMMIT() asm volatile("cp.async.commit_group;\n" ::: "memory")
#define CP_WAIT1()  asm volatile("cp.async.wait_group 1;\n" ::: "memory")
#define CP_WAIT0()  asm volatile("cp.async.wait_group 0;\n" ::: "memory")

__device__ __forceinline__ void ldsm4(uint32_t (&d)[4], uint32_t addr) {
    asm volatile("ldmatrix.sync.aligned.m8n8.x4.shared.b16 {%0,%1,%2,%3}, [%4];"
                 : "=r"(d[0]), "=r"(d[1]), "=r"(d[2]), "=r"(d[3]) : "r"(addr));
}

__device__ __forceinline__ float rna_tf32(float x) {
    uint32_t y;
    asm("cvt.rna.tf32.f32 %0, %1;" : "=r"(y) : "f"(x));
    return __uint_as_float(y);
}

__device__ __forceinline__ void mma_tf32(float (&c)[4], const uint32_t (&a)[4],
                                         uint32_t b0, uint32_t b1) {
    asm volatile(
        "mma.sync.aligned.m16n8k8.row.col.f32.tf32.tf32.f32 "
        "{%0,%1,%2,%3}, {%4,%5,%6,%7}, {%8,%9}, {%0,%1,%2,%3};"
        : "+f"(c[0]), "+f"(c[1]), "+f"(c[2]), "+f"(c[3])
        : "r"(a[0]), "r"(a[1]), "r"(a[2]), "r"(a[3]), "r"(b0), "r"(b1));
}

// --------------------------- prepass: RNA round ----------------------------

__global__ void __launch_bounds__(256)
round_tf32_kernel(const float* __restrict__ src, float* __restrict__ dst, int n4)
{
    const int stride = gridDim.x * blockDim.x;
    for (int i = blockIdx.x * blockDim.x + threadIdx.x; i < n4; i += stride) {
        float4 v = reinterpret_cast<const float4*>(src)[i];
        v.x = rna_tf32(v.x); v.y = rna_tf32(v.y);
        v.z = rna_tf32(v.z); v.w = rna_tf32(v.w);
        reinterpret_cast<float4*>(dst)[i] = v;
    }
}

// ------------------------------- main kernel -------------------------------

__global__ void __launch_bounds__(128, 2)
bilinear_tf32_kernel(const float* __restrict__ elg, const float* __restrict__ eth,
                     const float* __restrict__ Wm, float* __restrict__ out)
{
    extern __shared__ __align__(16) float smem[];
    const uint32_t sbase = smem_u32(smem);

    const int tid    = threadIdx.x;
    const int lane   = tid & 31;
    const int wid    = tid >> 5;      // 0..3
    const int warp_m = wid >> 1;      // 0..1
    const int warp_n = wid & 1;       // 0..1
    const size_t row0 = (size_t)blockIdx.x * BM;

    // ldmatrix per-lane byte offsets (t = tile index, r = row within tile)
    const int t = lane >> 3, r = lane & 7;
    const uint32_t aoff = (uint32_t)((((t & 1) * 8 + r) * ROWF + (t >> 1) * 4) * 4);
    const uint32_t boff = (uint32_t)((((t >> 1) * 8 + r) * ROWF + (t & 1) * 4) * 4);
    const uint32_t a_warp = (uint32_t)(warp_m * 64 * ROWF * 4);
    const uint32_t b_warp = (uint32_t)(warp_n * 64 * ROWF * 4);

    float acc[4][8][4];
    #pragma unroll
    for (int i = 0; i < 4; ++i)
        #pragma unroll
        for (int j = 0; j < 8; ++j)
            #pragma unroll
            for (int k = 0; k < 4; ++k) acc[i][j][k] = 0.0f;

    float part[8];
    #pragma unroll
    for (int i = 0; i < 8; ++i) part[i] = 0.0f;

    auto issue = [&](int jt) {
        const int nt = jt >> 5, kc = jt & 31, st = jt % NSTAGES;
        const uint32_t ab = sbase + st * STAGE_B;
        const uint32_t bb = ab + A_TILE_B;
        #pragma unroll
        for (int u = 0; u < 8; ++u) {               // A: 128 rows x 8 float4
            const int idx = tid + u * 128;          // 0..1023
            const int m = idx >> 3, c4 = idx & 7;
            cp16(ab + (uint32_t)((m * ROWF + c4 * 4) * 4),
                 eth + (row0 + m) * (size_t)DDIM + kc * BK + c4 * 4);
        }
        #pragma unroll
        for (int u = 0; u < 8; ++u) {               // B: 128 rows x 8 float4
            const int idx = tid + u * 128;
            const int n = idx >> 3, c4 = idx & 7;
            cp16(bb + (uint32_t)((n * ROWF + c4 * 4) * 4),
                 Wm + (size_t)(nt * BN + n) * DDIM + kc * BK + c4 * 4);
        }
        CP_COMMIT();
    };

    issue(0);
    issue(1);

    int cur = 0;
    for (int it = 0; it < TOT_IT; ++it) {
        const int nt = it >> 5, kc = it & 31;

        if (it == TOT_IT - 1) { CP_WAIT0(); } else { CP_WAIT1(); }
        __syncthreads();

        if (it + 2 < TOT_IT) issue(it + 2);

        const uint32_t abase = sbase + cur * STAGE_B + a_warp + aoff;
        const uint32_t bbase = sbase + cur * STAGE_B + A_TILE_B + b_warp + boff;

        #pragma unroll
        for (int ks = 0; ks < 4; ++ks) {
            uint32_t afr[4][4];
            #pragma unroll
            for (int fm = 0; fm < 4; ++fm)
                ldsm4(afr[fm], abase + (uint32_t)(fm * 16 * ROWF * 4 + ks * 32));
            uint32_t bfr[4][4];
            #pragma unroll
            for (int fp = 0; fp < 4; ++fp)
                ldsm4(bfr[fp], bbase + (uint32_t)(fp * 16 * ROWF * 4 + ks * 32));
            #pragma unroll
            for (int fm = 0; fm < 4; ++fm)
                #pragma unroll
                for (int fn = 0; fn < 8; ++fn)
                    mma_tf32(acc[fm][fn], afr[fm],
                             bfr[fn >> 1][(fn & 1) * 2 + 0],
                             bfr[fn >> 1][(fn & 1) * 2 + 1]);
        }
        cur = (cur + 1 == NSTAGES) ? 0 : cur + 1;

        // fused epilogue at the end of each n-tile: fold acc into row partials
        if (kc == KITERS - 1) {
            const int q = lane & 3, grp = lane >> 2;
            #pragma unroll
            for (int fm = 0; fm < 4; ++fm) {
                const size_t rowA = row0 + warp_m * 64 + fm * 16 + grp;
                #pragma unroll
                for (int fn = 0; fn < 8; ++fn) {
                    const int col = nt * BN + warp_n * 64 + fn * 8 + q * 2;
                    const float2 e0 = *reinterpret_cast<const float2*>(
                        elg + rowA * (size_t)DDIM + col);
                    const float2 e1 = *reinterpret_cast<const float2*>(
                        elg + (rowA + 8) * (size_t)DDIM + col);
                    part[fm * 2 + 0] = fmaf(acc[fm][fn][0], e0.x,
                                       fmaf(acc[fm][fn][1], e0.y, part[fm * 2 + 0]));
                    part[fm * 2 + 1] = fmaf(acc[fm][fn][2], e1.x,
                                       fmaf(acc[fm][fn][3], e1.y, part[fm * 2 + 1]));
                    acc[fm][fn][0] = 0.0f; acc[fm][fn][1] = 0.0f;
                    acc[fm][fn][2] = 0.0f; acc[fm][fn][3] = 0.0f;
                }
            }
        }
    }

    // cross-lane + cross-warp reduction (smem stages are dead now; reuse)
    __syncthreads();
    #pragma unroll
    for (int i = 0; i < 8; ++i) {
        part[i] += __shfl_xor_sync(0xFFFFFFFFu, part[i], 1);
        part[i] += __shfl_xor_sync(0xFFFFFFFFu, part[i], 2);
    }
    float* red = smem;                // [2][128]
    if ((lane & 3) == 0) {
        const int grp = lane >> 2;
        #pragma unroll
        for (int fm = 0; fm < 4; ++fm) {
            red[warp_n * 128 + warp_m * 64 + fm * 16 + grp]     = part[fm * 2 + 0];
            red[warp_n * 128 + warp_m * 64 + fm * 16 + grp + 8] = part[fm * 2 + 1];
        }
    }
    __syncthreads();
    out[row0 + tid] = red[tid] + red[128 + tid];
}

// ------------------------------- launch ------------------------------------

extern "C" void kernel_launch(void* const* d_in, const int* in_sizes, int n_in,
                              void* d_out, int out_size) {
    (void)in_sizes; (void)n_in; (void)out_size;
    const float* elg = (const float*)d_in[0];
    const float* eth = (const float*)d_in[1];
    const float* Wm  = (const float*)d_in[2];
    float* out = (float*)d_out;

    float* eth_t = nullptr;
    float* W_t   = nullptr;
    cudaGetSymbolAddress((void**)&eth_t, g_eth_t);
    cudaGetSymbolAddress((void**)&W_t,   g_W_t);

    // Prepass: RNA-round eth and W to tf32 once.
    round_tf32_kernel<<<1184, 256>>>(eth, eth_t, (NROWS * DDIM) / 4);
    round_tf32_kernel<<<148, 256>>>(Wm, W_t, (DDIM * DDIM) / 4);

    cudaFuncSetAttribute(bilinear_tf32_kernel,
                         cudaFuncAttributeMaxDynamicSharedMemorySize, SMEM_B);
    bilinear_tf32_kernel<<<NROWS / BM, 128, SMEM_B>>>(elg, eth_t, W_t, out);
}

// round 6
// speedup vs baseline: 1.7340x; 1.0347x over previous
#include <cuda_runtime.h>
#include <cstdint>

// ---------------------------------------------------------------------------
// out[n] = elg[n] @ W @ eth[n],  N=32768, D=1024, fp32.
// R6: R5 (128x128 CTA, 4 fat warps 64x64, 3-stage cp.async, 2 CTAs/SM) plus:
//  - eth RNA-rounding fused into n-tile 0 (A path: ld.global -> cvt -> smem +
//    g_eth_t); n-tiles 1..7 cp.async from the rounded copy. Separate eth
//    prepass eliminated (only the 4MB W prepass remains).
//  - L2 prefetch of the epilogue elg block a few iterations early.
// ---------------------------------------------------------------------------

static constexpr int NROWS = 32768;
static constexpr int DDIM  = 1024;
static constexpr int BM = 128, BN = 128, BK = 32;
static constexpr int NTILES  = DDIM / BN;            // 8
static constexpr int KITERS  = DDIM / BK;            // 32
static constexpr int TOT_IT  = NTILES * KITERS;      // 256

static constexpr int ROWF     = 36;                  // 32 floats + 4 pad
static constexpr int A_TILE_B = BM * ROWF * 4;       // 18432
static constexpr int B_TILE_B = BN * ROWF * 4;       // 18432
static constexpr int STAGE_B  = A_TILE_B + B_TILE_B; // 36864
static constexpr int STAGE_F  = STAGE_B / 4;
static constexpr int NSTAGES  = 3;
static constexpr int SMEM_B   = NSTAGES * STAGE_B;   // 110592

// Rounded copies (filled in-kernel for eth, by prepass for W). No allocs.
__device__ float g_eth_t[(size_t)NROWS * DDIM];      // 128 MB
__device__ float g_W_t[(size_t)DDIM * DDIM];         // 4 MB

__device__ __forceinline__ uint32_t smem_u32(const void* p) {
    uint32_t a;
    asm("{ .reg .u64 t; cvta.to.shared.u64 t, %1; cvt.u32.u64 %0, t; }" : "=r"(a) : "l"(p));
    return a;
}

__device__ __forceinline__ void cp16(uint32_t saddr, const void* g) {
    asm volatile("cp.async.cg.shared.global [%0], [%1], 16;\n" :: "r"(saddr), "l"(g));
}
#define CP_COMMIT() asm volatile("cp.async.commit_group;\n" ::: "memory")
#define CP_WAIT1()  asm volatile("cp.async.wait_group 1;\n" ::: "memory")
#define CP_WAIT0()  asm volatile("cp.async.wait_group 0;\n" ::: "memory")

__device__ __forceinline__ void ldsm4(uint32_t (&d)[4], uint32_t addr) {
    asm volatile("ldmatrix.sync.aligned.m8n8.x4.shared.b16 {%0,%1,%2,%3}, [%4];"
                 : "=r"(d[0]), "=r"(d[1]), "=r"(d[2]), "=r"(d[3]) : "r"(addr));
}

__device__ __forceinline__ float rna_tf32(float x) {
    uint32_t y;
    asm("cvt.rna.tf32.f32 %0, %1;" : "=r"(y) : "f"(x));
    return __uint_as_float(y);
}

__device__ __forceinline__ void prefetch_l2(const void* p) {
    asm volatile("prefetch.global.L2 [%0];" :: "l"(p));
}

__device__ __forceinline__ void mma_tf32(float (&c)[4], const uint32_t (&a)[4],
                                         uint32_t b0, uint32_t b1) {
    asm volatile(
        "mma.sync.aligned.m16n8k8.row.col.f32.tf32.tf32.f32 "
        "{%0,%1,%2,%3}, {%4,%5,%6,%7}, {%8,%9}, {%0,%1,%2,%3};"
        : "+f"(c[0]), "+f"(c[1]), "+f"(c[2]), "+f"(c[3])
        : "r"(a[0]), "r"(a[1]), "r"(a[2]), "r"(a[3]), "r"(b0), "r"(b1));
}

// --------------------------- prepass: RNA round (W only) -------------------

__global__ void __launch_bounds__(256)
round_tf32_kernel(const float* __restrict__ src, float* __restrict__ dst, int n4)
{
    const int stride = gridDim.x * blockDim.x;
    for (int i = blockIdx.x * blockDim.x + threadIdx.x; i < n4; i += stride) {
        float4 v = reinterpret_cast<const float4*>(src)[i];
        v.x = rna_tf32(v.x); v.y = rna_tf32(v.y);
        v.z = rna_tf32(v.z); v.w = rna_tf32(v.w);
        reinterpret_cast<float4*>(dst)[i] = v;
    }
}

// ------------------------------- main kernel -------------------------------

__global__ void __launch_bounds__(128, 2)
bilinear_tf32_kernel(const float* __restrict__ elg, const float* __restrict__ eth_raw,
                     float* __restrict__ eth_t, const float* __restrict__ Wm,
                     float* __restrict__ out)
{
    extern __shared__ __align__(16) float smem[];
    const uint32_t sbase = smem_u32(smem);

    const int tid    = threadIdx.x;
    const int lane   = tid & 31;
    const int wid    = tid >> 5;      // 0..3
    const int warp_m = wid >> 1;      // 0..1
    const int warp_n = wid & 1;       // 0..1
    const size_t row0 = (size_t)blockIdx.x * BM;

    // ldmatrix per-lane byte offsets (t = tile index, r = row within tile)
    const int t = lane >> 3, r = lane & 7;
    const uint32_t aoff = (uint32_t)((((t & 1) * 8 + r) * ROWF + (t >> 1) * 4) * 4);
    const uint32_t boff = (uint32_t)((((t >> 1) * 8 + r) * ROWF + (t & 1) * 4) * 4);
    const uint32_t a_warp = (uint32_t)(warp_m * 64 * ROWF * 4);
    const uint32_t b_warp = (uint32_t)(warp_n * 64 * ROWF * 4);

    float acc[4][8][4];
    #pragma unroll
    for (int i = 0; i < 4; ++i)
        #pragma unroll
        for (int j = 0; j < 8; ++j)
            #pragma unroll
            for (int k = 0; k < 4; ++k) acc[i][j][k] = 0.0f;

    float part[8];
    #pragma unroll
    for (int i = 0; i < 8; ++i) part[i] = 0.0f;

    // Issue loads for flattened iteration jt into stage jt%3.
    // jt < KITERS (n-tile 0): A path rounds raw eth -> smem + g_eth_t.
    // jt >= KITERS: A path cp.asyncs from the rounded copy.
    auto issue = [&](int jt) {
        const int nt = jt >> 5, kc = jt & 31, st = jt % NSTAGES;
        const uint32_t ab = sbase + st * STAGE_B;
        const uint32_t bb = ab + A_TILE_B;
        if (jt < KITERS) {
            const int a_f = st * STAGE_F;
            #pragma unroll
            for (int u = 0; u < 8; ++u) {
                const int idx = tid + u * 128;
                const int m = idx >> 3, c4 = idx & 7;
                const size_t goff = (row0 + m) * (size_t)DDIM + kc * BK + c4 * 4;
                float4 v = *reinterpret_cast<const float4*>(eth_raw + goff);
                v.x = rna_tf32(v.x); v.y = rna_tf32(v.y);
                v.z = rna_tf32(v.z); v.w = rna_tf32(v.w);
                *reinterpret_cast<float4*>(&smem[a_f + m * ROWF + c4 * 4]) = v;
                *reinterpret_cast<float4*>(eth_t + goff) = v;
            }
        } else {
            #pragma unroll
            for (int u = 0; u < 8; ++u) {
                const int idx = tid + u * 128;
                const int m = idx >> 3, c4 = idx & 7;
                cp16(ab + (uint32_t)((m * ROWF + c4 * 4) * 4),
                     eth_t + (row0 + m) * (size_t)DDIM + kc * BK + c4 * 4);
            }
        }
        #pragma unroll
        for (int u = 0; u < 8; ++u) {               // B: 128 rows x 8 float4
            const int idx = tid + u * 128;
            const int n = idx >> 3, c4 = idx & 7;
            cp16(bb + (uint32_t)((n * ROWF + c4 * 4) * 4),
                 Wm + (size_t)(nt * BN + n) * DDIM + kc * BK + c4 * 4);
        }
        CP_COMMIT();
    };

    issue(0);
    issue(1);

    int cur = 0;
    for (int it = 0; it < TOT_IT; ++it) {
        const int nt = it >> 5, kc = it & 31;

        if (it == TOT_IT - 1) { CP_WAIT0(); } else { CP_WAIT1(); }
        __syncthreads();

        if (it + 2 < TOT_IT) issue(it + 2);

        // Prefetch epilogue elg block into L2 a few iterations early.
        if (kc == 27) {
            const int q = lane & 3, grp = lane >> 2;
            const int col = nt * BN + warp_n * 64 + q * 2;
            #pragma unroll
            for (int fm = 0; fm < 4; ++fm) {
                const size_t rowA = row0 + warp_m * 64 + fm * 16 + grp;
                prefetch_l2(elg + rowA * (size_t)DDIM + col);
                prefetch_l2(elg + (rowA + 8) * (size_t)DDIM + col);
            }
        }

        const uint32_t abase = sbase + cur * STAGE_B + a_warp + aoff;
        const uint32_t bbase = sbase + cur * STAGE_B + A_TILE_B + b_warp + boff;

        #pragma unroll
        for (int ks = 0; ks < 4; ++ks) {
            uint32_t afr[4][4];
            #pragma unroll
            for (int fm = 0; fm < 4; ++fm)
                ldsm4(afr[fm], abase + (uint32_t)(fm * 16 * ROWF * 4 + ks * 32));
            uint32_t bfr[4][4];
            #pragma unroll
            for (int fp = 0; fp < 4; ++fp)
                ldsm4(bfr[fp], bbase + (uint32_t)(fp * 16 * ROWF * 4 + ks * 32));
            #pragma unroll
            for (int fm = 0; fm < 4; ++fm)
                #pragma unroll
                for (int fn = 0; fn < 8; ++fn)
                    mma_tf32(acc[fm][fn], afr[fm],
                             bfr[fn >> 1][(fn & 1) * 2 + 0],
                             bfr[fn >> 1][(fn & 1) * 2 + 1]);
        }
        cur = (cur + 1 == NSTAGES) ? 0 : cur + 1;

        // fused epilogue at the end of each n-tile: fold acc into row partials
        if (kc == KITERS - 1) {
            const int q = lane & 3, grp = lane >> 2;
            #pragma unroll
            for (int fm = 0; fm < 4; ++fm) {
                const size_t rowA = row0 + warp_m * 64 + fm * 16 + grp;
                #pragma unroll
                for (int fn = 0; fn < 8; ++fn) {
                    const int col = nt * BN + warp_n * 64 + fn * 8 + q * 2;
                    const float2 e0 = *reinterpret_cast<const float2*>(
                        elg + rowA * (size_t)DDIM + col);
                    const float2 e1 = *reinterpret_cast<const float2*>(
                        elg + (rowA + 8) * (size_t)DDIM + col);
                    part[fm * 2 + 0] = fmaf(acc[fm][fn][0], e0.x,
                                       fmaf(acc[fm][fn][1], e0.y, part[fm * 2 + 0]));
                    part[fm * 2 + 1] = fmaf(acc[fm][fn][2], e1.x,
                                       fmaf(acc[fm][fn][3], e1.y, part[fm * 2 + 1]));
                    acc[fm][fn][0] = 0.0f; acc[fm][fn][1] = 0.0f;
                    acc[fm][fn][2] = 0.0f; acc[fm][fn][3] = 0.0f;
                }
            }
        }
    }

    // cross-lane + cross-warp reduction (smem stages are dead now; reuse)
    __syncthreads();
    #pragma unroll
    for (int i = 0; i < 8; ++i) {
        part[i] += __shfl_xor_sync(0xFFFFFFFFu, part[i], 1);
        part[i] += __shfl_xor_sync(0xFFFFFFFFu, part[i], 2);
    }
    float* red = smem;                // [2][128]
    if ((lane & 3) == 0) {
        const int grp = lane >> 2;
        #pragma unroll
        for (int fm = 0; fm < 4; ++fm) {
            red[warp_n * 128 + warp_m * 64 + fm * 16 + grp]     = part[fm * 2 + 0];
            red[warp_n * 128 + warp_m * 64 + fm * 16 + grp + 8] = part[fm * 2 + 1];
        }
    }
    __syncthreads();
    out[row0 + tid] = red[tid] + red[128 + tid];
}

// ------------------------------- launch ------------------------------------

extern "C" void kernel_launch(void* const* d_in, const int* in_sizes, int n_in,
                              void* d_out, int out_size) {
    (void)in_sizes; (void)n_in; (void)out_size;
    const float* elg = (const float*)d_in[0];
    const float* eth = (const float*)d_in[1];
    const float* Wm  = (const float*)d_in[2];
    float* out = (float*)d_out;

    float* eth_t = nullptr;
    float* W_t   = nullptr;
    cudaGetSymbolAddress((void**)&eth_t, g_eth_t);
    cudaGetSymbolAddress((void**)&W_t,   g_W_t);

    // Prepass: RNA-round W only (4 MB). eth is rounded inside the main kernel.
    round_tf32_kernel<<<148, 256>>>(Wm, W_t, (DDIM * DDIM) / 4);

    cudaFuncSetAttribute(bilinear_tf32_kernel,
                         cudaFuncAttributeMaxDynamicSharedMemorySize, SMEM_B);
    bilinear_tf32_kernel<<<NROWS / BM, 128, SMEM_B>>>(elg, eth, eth_t, W_t, out);
}

// round 7
// speedup vs baseline: 1.7456x; 1.0067x over previous
#include <cuda_runtime.h>
#include <cstdint>

// ---------------------------------------------------------------------------
// out[n] = elg[n] @ W @ eth[n],  N=32768, D=1024, fp32.
// R7: R5 loop (128x128 CTA, 4 fat warps 64x64, 3-stage cp.async, 2 CTAs/SM)
// with register-light fused eth rounding: n-tile 0 cp.asyncs RAW eth, then an
// in-smem rounding sweep (LDS -> cvt.rna -> STS + STG to g_eth_t) before the
// MMAs; n-tiles 1..7 cp.async from the rounded copy. W prepass is 4 MB only.
// ---------------------------------------------------------------------------

static constexpr int NROWS = 32768;
static constexpr int DDIM  = 1024;
static constexpr int BM = 128, BN = 128, BK = 32;
static constexpr int NTILES  = DDIM / BN;            // 8
static constexpr int KITERS  = DDIM / BK;            // 32
static constexpr int TOT_IT  = NTILES * KITERS;      // 256

static constexpr int ROWF     = 36;                  // 32 floats + 4 pad
static constexpr int A_TILE_B = BM * ROWF * 4;       // 18432
static constexpr int B_TILE_B = BN * ROWF * 4;       // 18432
static constexpr int STAGE_B  = A_TILE_B + B_TILE_B; // 36864
static constexpr int STAGE_F  = STAGE_B / 4;
static constexpr int NSTAGES  = 3;
static constexpr int SMEM_B   = NSTAGES * STAGE_B;   // 110592

// Rounded copies (eth filled in-kernel, W by prepass). No allocs.
__device__ float g_eth_t[(size_t)NROWS * DDIM];      // 128 MB
__device__ float g_W_t[(size_t)DDIM * DDIM];         // 4 MB

__device__ __forceinline__ uint32_t smem_u32(const void* p) {
    uint32_t a;
    asm("{ .reg .u64 t; cvta.to.shared.u64 t, %1; cvt.u32.u64 %0, t; }" : "=r"(a) : "l"(p));
    return a;
}

__device__ __forceinline__ void cp16(uint32_t saddr, const void* g) {
    asm volatile("cp.async.cg.shared.global [%0], [%1], 16;\n" :: "r"(saddr), "l"(g));
}
#define CP_COMMIT() asm volatile("cp.async.commit_group;\n" ::: "memory")
#define CP_WAIT1()  asm volatile("cp.async.wait_group 1;\n" ::: "memory")
#define CP_WAIT0()  asm volatile("cp.async.wait_group 0;\n" ::: "memory")

__device__ __forceinline__ void ldsm4(uint32_t (&d)[4], uint32_t addr) {
    asm volatile("ldmatrix.sync.aligned.m8n8.x4.shared.b16 {%0,%1,%2,%3}, [%4];"
                 : "=r"(d[0]), "=r"(d[1]), "=r"(d[2]), "=r"(d[3]) : "r"(addr));
}

__device__ __forceinline__ float rna_tf32(float x) {
    uint32_t y;
    asm("cvt.rna.tf32.f32 %0, %1;" : "=r"(y) : "f"(x));
    return __uint_as_float(y);
}

__device__ __forceinline__ void prefetch_l2(const void* p) {
    asm volatile("prefetch.global.L2 [%0];" :: "l"(p));
}

__device__ __forceinline__ void mma_tf32(float (&c)[4], const uint32_t (&a)[4],
                                         uint32_t b0, uint32_t b1) {
    asm volatile(
        "mma.sync.aligned.m16n8k8.row.col.f32.tf32.tf32.f32 "
        "{%0,%1,%2,%3}, {%4,%5,%6,%7}, {%8,%9}, {%0,%1,%2,%3};"
        : "+f"(c[0]), "+f"(c[1]), "+f"(c[2]), "+f"(c[3])
        : "r"(a[0]), "r"(a[1]), "r"(a[2]), "r"(a[3]), "r"(b0), "r"(b1));
}

// --------------------------- prepass: RNA round (W only) -------------------

__global__ void __launch_bounds__(256)
round_tf32_kernel(const float* __restrict__ src, float* __restrict__ dst, int n4)
{
    const int stride = gridDim.x * blockDim.x;
    for (int i = blockIdx.x * blockDim.x + threadIdx.x; i < n4; i += stride) {
        float4 v = reinterpret_cast<const float4*>(src)[i];
        v.x = rna_tf32(v.x); v.y = rna_tf32(v.y);
        v.z = rna_tf32(v.z); v.w = rna_tf32(v.w);
        reinterpret_cast<float4*>(dst)[i] = v;
    }
}

// ------------------------------- main kernel -------------------------------

__global__ void __launch_bounds__(128, 2)
bilinear_tf32_kernel(const float* __restrict__ elg, const float* __restrict__ eth_raw,
                     float* __restrict__ eth_t, const float* __restrict__ Wm,
                     float* __restrict__ out)
{
    extern __shared__ __align__(16) float smem[];
    const uint32_t sbase = smem_u32(smem);

    const int tid    = threadIdx.x;
    const int lane   = tid & 31;
    const int wid    = tid >> 5;      // 0..3
    const int warp_m = wid >> 1;      // 0..1
    const int warp_n = wid & 1;       // 0..1
    const size_t row0 = (size_t)blockIdx.x * BM;

    // ldmatrix per-lane byte offsets (t = tile index, r = row within tile)
    const int t = lane >> 3, r = lane & 7;
    const uint32_t aoff = (uint32_t)((((t & 1) * 8 + r) * ROWF + (t >> 1) * 4) * 4);
    const uint32_t boff = (uint32_t)((((t >> 1) * 8 + r) * ROWF + (t & 1) * 4) * 4);
    const uint32_t a_warp = (uint32_t)(warp_m * 64 * ROWF * 4);
    const uint32_t b_warp = (uint32_t)(warp_n * 64 * ROWF * 4);

    float acc[4][8][4];
    #pragma unroll
    for (int i = 0; i < 4; ++i)
        #pragma unroll
        for (int j = 0; j < 8; ++j)
            #pragma unroll
            for (int k = 0; k < 4; ++k) acc[i][j][k] = 0.0f;

    float part[8];
    #pragma unroll
    for (int i = 0; i < 8; ++i) part[i] = 0.0f;

    // Issue cp.async loads for flattened iteration jt into stage jt%3.
    // nt 0 loads RAW eth (rounded in smem afterwards); nt>=1 loads rounded copy.
    auto issue = [&](int jt) {
        const int nt = jt >> 5, kc = jt & 31, st = jt % NSTAGES;
        const uint32_t ab = sbase + st * STAGE_B;
        const uint32_t bb = ab + A_TILE_B;
        const float* Asrc = (jt < KITERS) ? eth_raw : eth_t;
        #pragma unroll
        for (int u = 0; u < 8; ++u) {               // A: 128 rows x 8 float4
            const int idx = tid + u * 128;          // 0..1023
            const int m = idx >> 3, c4 = idx & 7;
            cp16(ab + (uint32_t)((m * ROWF + c4 * 4) * 4),
                 Asrc + (row0 + m) * (size_t)DDIM + kc * BK + c4 * 4);
        }
        #pragma unroll
        for (int u = 0; u < 8; ++u) {               // B: 128 rows x 8 float4
            const int idx = tid + u * 128;
            const int n = idx >> 3, c4 = idx & 7;
            cp16(bb + (uint32_t)((n * ROWF + c4 * 4) * 4),
                 Wm + (size_t)(nt * BN + n) * DDIM + kc * BK + c4 * 4);
        }
        CP_COMMIT();
    };

    issue(0);
    issue(1);

    int cur = 0;
    for (int it = 0; it < TOT_IT; ++it) {
        const int nt = it >> 5, kc = it & 31;

        if (it == TOT_IT - 1) { CP_WAIT0(); } else { CP_WAIT1(); }
        __syncthreads();

        if (it + 2 < TOT_IT) issue(it + 2);

        // n-tile 0: round the raw eth tile in smem, stream rounded copy out.
        if (it < KITERS) {
            const int a_f = cur * STAGE_F;
            #pragma unroll
            for (int u = 0; u < 8; ++u) {
                const int idx = tid + u * 128;
                const int m = idx >> 3, c4 = idx & 7;
                float4 v = *reinterpret_cast<const float4*>(&smem[a_f + m * ROWF + c4 * 4]);
                v.x = rna_tf32(v.x); v.y = rna_tf32(v.y);
                v.z = rna_tf32(v.z); v.w = rna_tf32(v.w);
                *reinterpret_cast<float4*>(&smem[a_f + m * ROWF + c4 * 4]) = v;
                *reinterpret_cast<float4*>(
                    eth_t + (row0 + m) * (size_t)DDIM + kc * BK + c4 * 4) = v;
            }
            __syncthreads();
        }

        // Prefetch epilogue elg block into L2 a few iterations early.
        if (kc == 27) {
            const int q = lane & 3, grp = lane >> 2;
            const int col = nt * BN + warp_n * 64 + q * 2;
            #pragma unroll
            for (int fm = 0; fm < 4; ++fm) {
                const size_t rowA = row0 + warp_m * 64 + fm * 16 + grp;
                prefetch_l2(elg + rowA * (size_t)DDIM + col);
                prefetch_l2(elg + (rowA + 8) * (size_t)DDIM + col);
            }
        }

        const uint32_t abase = sbase + cur * STAGE_B + a_warp + aoff;
        const uint32_t bbase = sbase + cur * STAGE_B + A_TILE_B + b_warp + boff;

        #pragma unroll
        for (int ks = 0; ks < 4; ++ks) {
            uint32_t afr[4][4];
            #pragma unroll
            for (int fm = 0; fm < 4; ++fm)
                ldsm4(afr[fm], abase + (uint32_t)(fm * 16 * ROWF * 4 + ks * 32));
            uint32_t bfr[4][4];
            #pragma unroll
            for (int fp = 0; fp < 4; ++fp)
                ldsm4(bfr[fp], bbase + (uint32_t)(fp * 16 * ROWF * 4 + ks * 32));
            #pragma unroll
            for (int fm = 0; fm < 4; ++fm)
                #pragma unroll
                for (int fn = 0; fn < 8; ++fn)
                    mma_tf32(acc[fm][fn], afr[fm],
                             bfr[fn >> 1][(fn & 1) * 2 + 0],
                             bfr[fn >> 1][(fn & 1) * 2 + 1]);
        }
        cur = (cur + 1 == NSTAGES) ? 0 : cur + 1;

        // fused epilogue at the end of each n-tile: fold acc into row partials
        if (kc == KITERS - 1) {
            const int q = lane & 3, grp = lane >> 2;
            #pragma unroll
            for (int fm = 0; fm < 4; ++fm) {
                const size_t rowA = row0 + warp_m * 64 + fm * 16 + grp;
                #pragma unroll
                for (int fn = 0; fn < 8; ++fn) {
                    const int col = nt * BN + warp_n * 64 + fn * 8 + q * 2;
                    const float2 e0 = *reinterpret_cast<const float2*>(
                        elg + rowA * (size_t)DDIM + col);
                    const float2 e1 = *reinterpret_cast<const float2*>(
                        elg + (rowA + 8) * (size_t)DDIM + col);
                    part[fm * 2 + 0] = fmaf(acc[fm][fn][0], e0.x,
                                       fmaf(acc[fm][fn][1], e0.y, part[fm * 2 + 0]));
                    part[fm * 2 + 1] = fmaf(acc[fm][fn][2], e1.x,
                                       fmaf(acc[fm][fn][3], e1.y, part[fm * 2 + 1]));
                    acc[fm][fn][0] = 0.0f; acc[fm][fn][1] = 0.0f;
                    acc[fm][fn][2] = 0.0f; acc[fm][fn][3] = 0.0f;
                }
            }
        }
    }

    // cross-lane + cross-warp reduction (smem stages are dead now; reuse)
    __syncthreads();
    #pragma unroll
    for (int i = 0; i < 8; ++i) {
        part[i] += __shfl_xor_sync(0xFFFFFFFFu, part[i], 1);
        part[i] += __shfl_xor_sync(0xFFFFFFFFu, part[i], 2);
    }
    float* red = smem;                // [2][128]
    if ((lane & 3) == 0) {
        const int grp = lane >> 2;
        #pragma unroll
        for (int fm = 0; fm < 4; ++fm) {
            red[warp_n * 128 + warp_m * 64 + fm * 16 + grp]     = part[fm * 2 + 0];
            red[warp_n * 128 + warp_m * 64 + fm * 16 + grp + 8] = part[fm * 2 + 1];
        }
    }
    __syncthreads();
    out[row0 + tid] = red[tid] + red[128 + tid];
}

// ------------------------------- launch ------------------------------------

extern "C" void kernel_launch(void* const* d_in, const int* in_sizes, int n_in,
                              void* d_out, int out_size) {
    (void)in_sizes; (void)n_in; (void)out_size;
    const float* elg = (const float*)d_in[0];
    const float* eth = (const float*)d_in[1];
    const float* Wm  = (const float*)d_in[2];
    float* out = (float*)d_out;

    float* eth_t = nullptr;
    float* W_t   = nullptr;
    cudaGetSymbolAddress((void**)&eth_t, g_eth_t);
    cudaGetSymbolAddress((void**)&W_t,   g_W_t);

    // Prepass: RNA-round W only (4 MB). eth is rounded inside the main kernel.
    round_tf32_kernel<<<148, 256>>>(Wm, W_t, (DDIM * DDIM) / 4);

    cudaFuncSetAttribute(bilinear_tf32_kernel,
                         cudaFuncAttributeMaxDynamicSharedMemorySize, SMEM_B);
    bilinear_tf32_kernel<<<NROWS / BM, 128, SMEM_B>>>(elg, eth, eth_t, W_t, out);
}

// round 9
// speedup vs baseline: 1.9903x; 1.1401x over previous
#include <cuda_runtime.h>
#include <cstdint>

// ---------------------------------------------------------------------------
// out[n] = elg[n] @ W @ eth[n],  N=32768, D=1024, fp32.
// R8: R5 hot loop (128x128 tile, 4 fat warps 64x64, 3-stage cp.async,
// 2 CTAs/SM) with:
//  - raw eth fed to mma (HW tf32 truncation); only W is RNA-rounded (4MB).
//  - grid (256,4): each CTA does 2 n-tiles (64 iters) for fine load balance;
//    partial outputs combined with atomicAdd into a zero-filled out.
// ---------------------------------------------------------------------------

static constexpr int NROWS = 32768;
static constexpr int DDIM  = 1024;
static constexpr int BM = 128, BN = 128, BK = 32;
static constexpr int KITERS  = DDIM / BK;            // 32
static constexpr int NT_PER  = 2;                    // n-tiles per CTA
static constexpr int TOT_IT  = NT_PER * KITERS;      // 64

static constexpr int ROWF     = 36;                  // 32 floats + 4 pad
static constexpr int A_TILE_B = BM * ROWF * 4;       // 18432
static constexpr int B_TILE_B = BN * ROWF * 4;       // 18432
static constexpr int STAGE_B  = A_TILE_B + B_TILE_B; // 36864
static constexpr int NSTAGES  = 3;
static constexpr int SMEM_B   = NSTAGES * STAGE_B;   // 110592

__device__ float g_W_t[(size_t)DDIM * DDIM];         // 4 MB rounded W

__device__ __forceinline__ uint32_t smem_u32(const void* p) {
    uint32_t a;
    asm("{ .reg .u64 t; cvta.to.shared.u64 t, %1; cvt.u32.u64 %0, t; }" : "=r"(a) : "l"(p));
    return a;
}

__device__ __forceinline__ void cp16(uint32_t saddr, const void* g) {
    asm volatile("cp.async.cg.shared.global [%0], [%1], 16;\n" :: "r"(saddr), "l"(g));
}
#define CP_COMMIT() asm volatile("cp.async.commit_group;\n" ::: "memory")
#define CP_WAIT1()  asm volatile("cp.async.wait_group 1;\n" ::: "memory")
#define CP_WAIT0()  asm volatile("cp.async.wait_group 0;\n" ::: "memory")

__device__ __forceinline__ void ldsm4(uint32_t (&d)[4], uint32_t addr) {
    asm volatile("ldmatrix.sync.aligned.m8n8.x4.shared.b16 {%0,%1,%2,%3}, [%4];"
                 : "=r"(d[0]), "=r"(d[1]), "=r"(d[2]), "=r"(d[3]) : "r"(addr));
}

__device__ __forceinline__ float rna_tf32(float x) {
    uint32_t y;
    asm("cvt.rna.tf32.f32 %0, %1;" : "=r"(y) : "f"(x));
    return __uint_as_float(y);
}

__device__ __forceinline__ void prefetch_l2(const void* p) {
    asm volatile("prefetch.global.L2 [%0];" :: "l"(p));
}

__device__ __forceinline__ void mma_tf32(float (&c)[4], const uint32_t (&a)[4],
                                         uint32_t b0, uint32_t b1) {
    asm volatile(
        "mma.sync.aligned.m16n8k8.row.col.f32.tf32.tf32.f32 "
        "{%0,%1,%2,%3}, {%4,%5,%6,%7}, {%8,%9}, {%0,%1,%2,%3};"
        : "+f"(c[0]), "+f"(c[1]), "+f"(c[2]), "+f"(c[3])
        : "r"(a[0]), "r"(a[1]), "r"(a[2]), "r"(a[3]), "r"(b0), "r"(b1));
}

// --------------------------- helpers: prepass + zero -----------------------

__global__ void __launch_bounds__(256)
round_tf32_kernel(const float* __restrict__ src, float* __restrict__ dst, int n4)
{
    const int stride = gridDim.x * blockDim.x;
    for (int i = blockIdx.x * blockDim.x + threadIdx.x; i < n4; i += stride) {
        float4 v = reinterpret_cast<const float4*>(src)[i];
        v.x = rna_tf32(v.x); v.y = rna_tf32(v.y);
        v.z = rna_tf32(v.z); v.w = rna_tf32(v.w);
        reinterpret_cast<float4*>(dst)[i] = v;
    }
}

__global__ void __launch_bounds__(256)
zero_kernel(float* __restrict__ dst, int n4)
{
    const int i = blockIdx.x * blockDim.x + threadIdx.x;
    if (i < n4) reinterpret_cast<float4*>(dst)[i] = make_float4(0.f, 0.f, 0.f, 0.f);
}

// ------------------------------- main kernel -------------------------------

__global__ void __launch_bounds__(128, 2)
bilinear_tf32_kernel(const float* __restrict__ elg, const float* __restrict__ eth,
                     const float* __restrict__ Wm, float* __restrict__ out)
{
    extern __shared__ __align__(16) float smem[];
    const uint32_t sbase = smem_u32(smem);

    const int tid    = threadIdx.x;
    const int lane   = tid & 31;
    const int wid    = tid >> 5;      // 0..3
    const int warp_m = wid >> 1;      // 0..1
    const int warp_n = wid & 1;       // 0..1
    const size_t row0 = (size_t)blockIdx.x * BM;
    const int nt0 = blockIdx.y * NT_PER;

    // ldmatrix per-lane byte offsets (t = tile index, r = row within tile)
    const int t = lane >> 3, r = lane & 7;
    const uint32_t aoff = (uint32_t)((((t & 1) * 8 + r) * ROWF + (t >> 1) * 4) * 4);
    const uint32_t boff = (uint32_t)((((t >> 1) * 8 + r) * ROWF + (t & 1) * 4) * 4);
    const uint32_t a_warp = (uint32_t)(warp_m * 64 * ROWF * 4);
    const uint32_t b_warp = (uint32_t)(warp_n * 64 * ROWF * 4);

    float acc[4][8][4];
    #pragma unroll
    for (int i = 0; i < 4; ++i)
        #pragma unroll
        for (int j = 0; j < 8; ++j)
            #pragma unroll
            for (int k = 0; k < 4; ++k) acc[i][j][k] = 0.0f;

    float part[8];
    #pragma unroll
    for (int i = 0; i < 8; ++i) part[i] = 0.0f;

    auto issue = [&](int jt) {
        const int nt = nt0 + (jt >> 5), kc = jt & 31, st = jt % NSTAGES;
        const uint32_t ab = sbase + st * STAGE_B;
        const uint32_t bb = ab + A_TILE_B;
        #pragma unroll
        for (int u = 0; u < 8; ++u) {               // A: 128 rows x 8 float4 (raw eth)
            const int idx = tid + u * 128;          // 0..1023
            const int m = idx >> 3, c4 = idx & 7;
            cp16(ab + (uint32_t)((m * ROWF + c4 * 4) * 4),
                 eth + (row0 + m) * (size_t)DDIM + kc * BK + c4 * 4);
        }
        #pragma unroll
        for (int u = 0; u < 8; ++u) {               // B: 128 rows x 8 float4 (rounded W)
            const int idx = tid + u * 128;
            const int n = idx >> 3, c4 = idx & 7;
            cp16(bb + (uint32_t)((n * ROWF + c4 * 4) * 4),
                 Wm + (size_t)(nt * BN + n) * DDIM + kc * BK + c4 * 4);
        }
        CP_COMMIT();
    };

    issue(0);
    issue(1);

    int cur = 0;
    for (int it = 0; it < TOT_IT; ++it) {
        const int nt = nt0 + (it >> 5), kc = it & 31;

        if (it == TOT_IT - 1) { CP_WAIT0(); } else { CP_WAIT1(); }
        __syncthreads();

        if (it + 2 < TOT_IT) issue(it + 2);

        // Prefetch epilogue elg block into L2 a few iterations early.
        if (kc == 27) {
            const int q = lane & 3, grp = lane >> 2;
            const int col = nt * BN + warp_n * 64 + q * 2;
            #pragma unroll
            for (int fm = 0; fm < 4; ++fm) {
                const size_t rowA = row0 + warp_m * 64 + fm * 16 + grp;
                prefetch_l2(elg + rowA * (size_t)DDIM + col);
                prefetch_l2(elg + (rowA + 8) * (size_t)DDIM + col);
            }
        }

        const uint32_t abase = sbase + cur * STAGE_B + a_warp + aoff;
        const uint32_t bbase = sbase + cur * STAGE_B + A_TILE_B + b_warp + boff;

        #pragma unroll
        for (int ks = 0; ks < 4; ++ks) {
            uint32_t afr[4][4];
            #pragma unroll
            for (int fm = 0; fm < 4; ++fm)
                ldsm4(afr[fm], abase + (uint32_t)(fm * 16 * ROWF * 4 + ks * 32));
            uint32_t bfr[4][4];
            #pragma unroll
            for (int fp = 0; fp < 4; ++fp)
                ldsm4(bfr[fp], bbase + (uint32_t)(fp * 16 * ROWF * 4 + ks * 32));
            #pragma unroll
            for (int fm = 0; fm < 4; ++fm)
                #pragma unroll
                for (int fn = 0; fn < 8; ++fn)
                    mma_tf32(acc[fm][fn], afr[fm],
                             bfr[fn >> 1][(fn & 1) * 2 + 0],
                             bfr[fn >> 1][(fn & 1) * 2 + 1]);
        }
        cur = (cur + 1 == NSTAGES) ? 0 : cur + 1;

        // fused epilogue at the end of each n-tile: fold acc into row partials
        if (kc == KITERS - 1) {
            const int q = lane & 3, grp = lane >> 2;
            #pragma unroll
            for (int fm = 0; fm < 4; ++fm) {
                const size_t rowA = row0 + warp_m * 64 + fm * 16 + grp;
                #pragma unroll
                for (int fn = 0; fn < 8; ++fn) {
                    const int col = nt * BN + warp_n * 64 + fn * 8 + q * 2;
                    const float2 e0 = *reinterpret_cast<const float2*>(
                        elg + rowA * (size_t)DDIM + col);
                    const float2 e1 = *reinterpret_cast<const float2*>(
                        elg + (rowA + 8) * (size_t)DDIM + col);
                    part[fm * 2 + 0] = fmaf(acc[fm][fn][0], e0.x,
                                       fmaf(acc[fm][fn][1], e0.y, part[fm * 2 + 0]));
                    part[fm * 2 + 1] = fmaf(acc[fm][fn][2], e1.x,
                                       fmaf(acc[fm][fn][3], e1.y, part[fm * 2 + 1]));
                    acc[fm][fn][0] = 0.0f; acc[fm][fn][1] = 0.0f;
                    acc[fm][fn][2] = 0.0f; acc[fm][fn][3] = 0.0f;
                }
            }
        }
    }

    // cross-lane + cross-warp reduction, then atomic accumulate to out
    __syncthreads();
    #pragma unroll
    for (int i = 0; i < 8; ++i) {
        part[i] += __shfl_xor_sync(0xFFFFFFFFu, part[i], 1);
        part[i] += __shfl_xor_sync(0xFFFFFFFFu, part[i], 2);
    }
    float* red = smem;                // [2][128]
    if ((lane & 3) == 0) {
        const int grp = lane >> 2;
        #pragma unroll
        for (int fm = 0; fm < 4; ++fm) {
            red[warp_n * 128 + warp_m * 64 + fm * 16 + grp]     = part[fm * 2 + 0];
            red[warp_n * 128 + warp_m * 64 + fm * 16 + grp + 8] = part[fm * 2 + 1];
        }
    }
    __syncthreads();
    atomicAdd(&out[row0 + tid], red[tid] + red[128 + tid]);
}

// ------------------------------- launch ------------------------------------

extern "C" void kernel_launch(void* const* d_in, const int* in_sizes, int n_in,
                              void* d_out, int out_size) {
    (void)in_sizes; (void)n_in; (void)out_size;
    const float* elg = (const float*)d_in[0];
    const float* eth = (const float*)d_in[1];
    const float* Wm  = (const float*)d_in[2];
    float* out = (float*)d_out;

    float* W_t = nullptr;
    cudaGetSymbolAddress((void**)&W_t, g_W_t);

    // Prepass: RNA-round W (4 MB); zero the output accumulators.
    round_tf32_kernel<<<148, 256>>>(Wm, W_t, (DDIM * DDIM) / 4);
    zero_kernel<<<(NROWS / 4 + 255) / 256, 256>>>(out, NROWS / 4);

    cudaFuncSetAttribute(bilinear_tf32_kernel,
                         cudaFuncAttributeMaxDynamicSharedMemorySize, SMEM_B);
    dim3 grid(NROWS / BM, DDIM / (BN * NT_PER));
    bilinear_tf32_kernel<<<grid, 128, SMEM_B>>>(elg, eth, W_t, out);
}

// round 10
// speedup vs baseline: 2.1128x; 1.0616x over previous
#include <cuda_runtime.h>
#include <cstdint>

// ---------------------------------------------------------------------------
// out[n] = elg[n] @ W @ eth[n],  N=32768, D=1024, fp32.
// R9: R8 hot loop (128x128 tile, 4 fat warps 64x64, 3-stage cp.async,
// 2 CTAs/SM, raw eth + RNA-rounded W) with finer work split:
//  - NT_PER=1: grid (8, 256), nt = blockIdx.x (fastest) -> 2048 CTAs,
//    ~7 per resident slot: makespan quantization ~1-2% instead of ~15%,
//    and the 8 nt-CTAs of a row block run near-concurrently so eth is
//    DRAM-read ~once (W is L2-resident).
//  - single merged prep kernel: rounds W and zeroes out.
// ---------------------------------------------------------------------------

static constexpr int NROWS = 32768;
static constexpr int DDIM  = 1024;
static constexpr int BM = 128, BN = 128, BK = 32;
static constexpr int KITERS  = DDIM / BK;            // 32
static constexpr int TOT_IT  = KITERS;               // 32 (one n-tile per CTA)

static constexpr int ROWF     = 36;                  // 32 floats + 4 pad
static constexpr int A_TILE_B = BM * ROWF * 4;       // 18432
static constexpr int B_TILE_B = BN * ROWF * 4;       // 18432
static constexpr int STAGE_B  = A_TILE_B + B_TILE_B; // 36864
static constexpr int NSTAGES  = 3;
static constexpr int SMEM_B   = NSTAGES * STAGE_B;   // 110592

__device__ float g_W_t[(size_t)DDIM * DDIM];         // 4 MB rounded W

__device__ __forceinline__ uint32_t smem_u32(const void* p) {
    uint32_t a;
    asm("{ .reg .u64 t; cvta.to.shared.u64 t, %1; cvt.u32.u64 %0, t; }" : "=r"(a) : "l"(p));
    return a;
}

__device__ __forceinline__ void cp16(uint32_t saddr, const void* g) {
    asm volatile("cp.async.cg.shared.global [%0], [%1], 16;\n" :: "r"(saddr), "l"(g));
}
#define CP_COMMIT() asm volatile("cp.async.commit_group;\n" ::: "memory")
#define CP_WAIT1()  asm volatile("cp.async.wait_group 1;\n" ::: "memory")
#define CP_WAIT0()  asm volatile("cp.async.wait_group 0;\n" ::: "memory")

__device__ __forceinline__ void ldsm4(uint32_t (&d)[4], uint32_t addr) {
    asm volatile("ldmatrix.sync.aligned.m8n8.x4.shared.b16 {%0,%1,%2,%3}, [%4];"
                 : "=r"(d[0]), "=r"(d[1]), "=r"(d[2]), "=r"(d[3]) : "r"(addr));
}

__device__ __forceinline__ float rna_tf32(float x) {
    uint32_t y;
    asm("cvt.rna.tf32.f32 %0, %1;" : "=r"(y) : "f"(x));
    return __uint_as_float(y);
}

__device__ __forceinline__ void prefetch_l2(const void* p) {
    asm volatile("prefetch.global.L2 [%0];" :: "l"(p));
}

__device__ __forceinline__ void mma_tf32(float (&c)[4], const uint32_t (&a)[4],
                                         uint32_t b0, uint32_t b1) {
    asm volatile(
        "mma.sync.aligned.m16n8k8.row.col.f32.tf32.tf32.f32 "
        "{%0,%1,%2,%3}, {%4,%5,%6,%7}, {%8,%9}, {%0,%1,%2,%3};"
        : "+f"(c[0]), "+f"(c[1]), "+f"(c[2]), "+f"(c[3])
        : "r"(a[0]), "r"(a[1]), "r"(a[2]), "r"(a[3]), "r"(b0), "r"(b1));
}

// ---------------- prep: RNA-round W (4 MB) + zero out (128 KB) -------------

static constexpr int W4   = (DDIM * DDIM) / 4;       // 262144 float4
static constexpr int OUT4 = NROWS / 4;               // 8192 float4

__global__ void __launch_bounds__(256)
prep_kernel(const float* __restrict__ Wsrc, float* __restrict__ Wdst,
            float* __restrict__ outz)
{
    const int gid = blockIdx.x * blockDim.x + threadIdx.x;
    const int stride = gridDim.x * blockDim.x;
    for (int i = gid; i < W4; i += stride) {
        float4 v = reinterpret_cast<const float4*>(Wsrc)[i];
        v.x = rna_tf32(v.x); v.y = rna_tf32(v.y);
        v.z = rna_tf32(v.z); v.w = rna_tf32(v.w);
        reinterpret_cast<float4*>(Wdst)[i] = v;
    }
    for (int i = gid; i < OUT4; i += stride)
        reinterpret_cast<float4*>(outz)[i] = make_float4(0.f, 0.f, 0.f, 0.f);
}

// ------------------------------- main kernel -------------------------------

__global__ void __launch_bounds__(128, 2)
bilinear_tf32_kernel(const float* __restrict__ elg, const float* __restrict__ eth,
                     const float* __restrict__ Wm, float* __restrict__ out)
{
    extern __shared__ __align__(16) float smem[];
    const uint32_t sbase = smem_u32(smem);

    const int tid    = threadIdx.x;
    const int lane   = tid & 31;
    const int wid    = tid >> 5;      // 0..3
    const int warp_m = wid >> 1;      // 0..1
    const int warp_n = wid & 1;       // 0..1
    const int nt     = blockIdx.x;    // 0..7 (fastest-varying)
    const size_t row0 = (size_t)blockIdx.y * BM;

    // ldmatrix per-lane byte offsets (t = tile index, r = row within tile)
    const int t = lane >> 3, r = lane & 7;
    const uint32_t aoff = (uint32_t)((((t & 1) * 8 + r) * ROWF + (t >> 1) * 4) * 4);
    const uint32_t boff = (uint32_t)((((t >> 1) * 8 + r) * ROWF + (t & 1) * 4) * 4);
    const uint32_t a_warp = (uint32_t)(warp_m * 64 * ROWF * 4);
    const uint32_t b_warp = (uint32_t)(warp_n * 64 * ROWF * 4);

    float acc[4][8][4];
    #pragma unroll
    for (int i = 0; i < 4; ++i)
        #pragma unroll
        for (int j = 0; j < 8; ++j)
            #pragma unroll
            for (int k = 0; k < 4; ++k) acc[i][j][k] = 0.0f;

    auto issue = [&](int jt) {
        const int kc = jt, st = jt % NSTAGES;
        const uint32_t ab = sbase + st * STAGE_B;
        const uint32_t bb = ab + A_TILE_B;
        #pragma unroll
        for (int u = 0; u < 8; ++u) {               // A: 128 rows x 8 float4 (raw eth)
            const int idx = tid + u * 128;          // 0..1023
            const int m = idx >> 3, c4 = idx & 7;
            cp16(ab + (uint32_t)((m * ROWF + c4 * 4) * 4),
                 eth + (row0 + m) * (size_t)DDIM + kc * BK + c4 * 4);
        }
        #pragma unroll
        for (int u = 0; u < 8; ++u) {               // B: 128 rows x 8 float4 (rounded W)
            const int idx = tid + u * 128;
            const int n = idx >> 3, c4 = idx & 7;
            cp16(bb + (uint32_t)((n * ROWF + c4 * 4) * 4),
                 Wm + (size_t)(nt * BN + n) * DDIM + kc * BK + c4 * 4);
        }
        CP_COMMIT();
    };

    issue(0);
    issue(1);

    int cur = 0;
    for (int it = 0; it < TOT_IT; ++it) {
        if (it == TOT_IT - 1) { CP_WAIT0(); } else { CP_WAIT1(); }
        __syncthreads();

        if (it + 2 < TOT_IT) issue(it + 2);

        // Prefetch epilogue elg block into L2 a few iterations early.
        if (it == 27) {
            const int q = lane & 3, grp = lane >> 2;
            const int col = nt * BN + warp_n * 64 + q * 2;
            #pragma unroll
            for (int fm = 0; fm < 4; ++fm) {
                const size_t rowA = row0 + warp_m * 64 + fm * 16 + grp;
                prefetch_l2(elg + rowA * (size_t)DDIM + col);
                prefetch_l2(elg + (rowA + 8) * (size_t)DDIM + col);
            }
        }

        const uint32_t abase = sbase + cur * STAGE_B + a_warp + aoff;
        const uint32_t bbase = sbase + cur * STAGE_B + A_TILE_B + b_warp + boff;

        #pragma unroll
        for (int ks = 0; ks < 4; ++ks) {
            uint32_t afr[4][4];
            #pragma unroll
            for (int fm = 0; fm < 4; ++fm)
                ldsm4(afr[fm], abase + (uint32_t)(fm * 16 * ROWF * 4 + ks * 32));
            uint32_t bfr[4][4];
            #pragma unroll
            for (int fp = 0; fp < 4; ++fp)
                ldsm4(bfr[fp], bbase + (uint32_t)(fp * 16 * ROWF * 4 + ks * 32));
            #pragma unroll
            for (int fm = 0; fm < 4; ++fm)
                #pragma unroll
                for (int fn = 0; fn < 8; ++fn)
                    mma_tf32(acc[fm][fn], afr[fm],
                             bfr[fn >> 1][(fn & 1) * 2 + 0],
                             bfr[fn >> 1][(fn & 1) * 2 + 1]);
        }
        cur = (cur + 1 == NSTAGES) ? 0 : cur + 1;
    }

    // Epilogue: fold acc into per-row partials against elg, reduce, atomicAdd.
    float part[8];
    #pragma unroll
    for (int i = 0; i < 8; ++i) part[i] = 0.0f;
    {
        const int q = lane & 3, grp = lane >> 2;
        #pragma unroll
        for (int fm = 0; fm < 4; ++fm) {
            const size_t rowA = row0 + warp_m * 64 + fm * 16 + grp;
            #pragma unroll
            for (int fn = 0; fn < 8; ++fn) {
                const int col = nt * BN + warp_n * 64 + fn * 8 + q * 2;
                const float2 e0 = *reinterpret_cast<const float2*>(
                    elg + rowA * (size_t)DDIM + col);
                const float2 e1 = *reinterpret_cast<const float2*>(
                    elg + (rowA + 8) * (size_t)DDIM + col);
                part[fm * 2 + 0] = fmaf(acc[fm][fn][0], e0.x,
                                   fmaf(acc[fm][fn][1], e0.y, part[fm * 2 + 0]));
                part[fm * 2 + 1] = fmaf(acc[fm][fn][2], e1.x,
                                   fmaf(acc[fm][fn][3], e1.y, part[fm * 2 + 1]));
            }
        }
    }

    __syncthreads();
    #pragma unroll
    for (int i = 0; i < 8; ++i) {
        part[i] += __shfl_xor_sync(0xFFFFFFFFu, part[i], 1);
        part[i] += __shfl_xor_sync(0xFFFFFFFFu, part[i], 2);
    }
    float* red = smem;                // [2][128]
    if ((lane & 3) == 0) {
        const int grp = lane >> 2;
        #pragma unroll
        for (int fm = 0; fm < 4; ++fm) {
            red[warp_n * 128 + warp_m * 64 + fm * 16 + grp]     = part[fm * 2 + 0];
            red[warp_n * 128 + warp_m * 64 + fm * 16 + grp + 8] = part[fm * 2 + 1];
        }
    }
    __syncthreads();
    atomicAdd(&out[row0 + tid], red[tid] + red[128 + tid]);
}

// ------------------------------- launch ------------------------------------

extern "C" void kernel_launch(void* const* d_in, const int* in_sizes, int n_in,
                              void* d_out, int out_size) {
    (void)in_sizes; (void)n_in; (void)out_size;
    const float* elg = (const float*)d_in[0];
    const float* eth = (const float*)d_in[1];
    const float* Wm  = (const float*)d_in[2];
    float* out = (float*)d_out;

    float* W_t = nullptr;
    cudaGetSymbolAddress((void**)&W_t, g_W_t);

    prep_kernel<<<148, 256>>>(Wm, W_t, out);

    cudaFuncSetAttribute(bilinear_tf32_kernel,
                         cudaFuncAttributeMaxDynamicSharedMemorySize, SMEM_B);
    dim3 grid(DDIM / BN, NROWS / BM);   // x = n-tile (fastest), y = row block
    bilinear_tf32_kernel<<<grid, 128, SMEM_B>>>(elg, eth, W_t, out);
}